// round 1
// baseline (speedup 1.0000x reference)
#include <cuda_runtime.h>

// y[token, o] = sum_e cos(x[token, e] + theta[e]) * W[o, e]
// tokens = 128 * 8192 = 1,048,576 ; E = O = 16
//
// One thread per token. x read as 4x float4, theta + W staged in shared
// (broadcast LDS), fast __cosf, output packed as 4x float4.

#define EMBED 16
#define TOKENS (128 * 8192)
#define BLOCK 256

__global__ __launch_bounds__(BLOCK) void qattn_kernel(
    const float4* __restrict__ x4,      // [TOKENS * 4] float4
    const float*  __restrict__ theta,   // [16]
    const float4* __restrict__ w4,      // [16 rows][4 quads] row-major W[o][e]
    float4*       __restrict__ y4)      // [TOKENS * 4]
{
    __shared__ float  s_th[EMBED];
    __shared__ float4 s_w[EMBED][4];    // s_w[o][q]

    int t = threadIdx.x;
    if (t < EMBED)      s_th[t] = theta[t];
    if (t < EMBED * 4)  ((float4*)s_w)[t] = w4[t];
    __syncthreads();

    int token = blockIdx.x * BLOCK + threadIdx.x;
    // grid exactly covers TOKENS; no tail check needed (TOKENS % BLOCK == 0)

    const float4* xp = x4 + (size_t)token * 4;
    float4 a0 = xp[0];
    float4 a1 = xp[1];
    float4 a2 = xp[2];
    float4 a3 = xp[3];

    float z[EMBED];
    z[ 0] = __cosf(a0.x + s_th[ 0]);
    z[ 1] = __cosf(a0.y + s_th[ 1]);
    z[ 2] = __cosf(a0.z + s_th[ 2]);
    z[ 3] = __cosf(a0.w + s_th[ 3]);
    z[ 4] = __cosf(a1.x + s_th[ 4]);
    z[ 5] = __cosf(a1.y + s_th[ 5]);
    z[ 6] = __cosf(a1.z + s_th[ 6]);
    z[ 7] = __cosf(a1.w + s_th[ 7]);
    z[ 8] = __cosf(a2.x + s_th[ 8]);
    z[ 9] = __cosf(a2.y + s_th[ 9]);
    z[10] = __cosf(a2.z + s_th[10]);
    z[11] = __cosf(a2.w + s_th[11]);
    z[12] = __cosf(a3.x + s_th[12]);
    z[13] = __cosf(a3.y + s_th[13]);
    z[14] = __cosf(a3.z + s_th[14]);
    z[15] = __cosf(a3.w + s_th[15]);

    float out[EMBED];
    #pragma unroll
    for (int o = 0; o < EMBED; ++o) {
        float4 w0 = s_w[o][0];
        float4 w1 = s_w[o][1];
        float4 w2 = s_w[o][2];
        float4 w3 = s_w[o][3];
        float acc;
        acc  = z[ 0] * w0.x;
        acc = fmaf(z[ 1], w0.y, acc);
        acc = fmaf(z[ 2], w0.z, acc);
        acc = fmaf(z[ 3], w0.w, acc);
        acc = fmaf(z[ 4], w1.x, acc);
        acc = fmaf(z[ 5], w1.y, acc);
        acc = fmaf(z[ 6], w1.z, acc);
        acc = fmaf(z[ 7], w1.w, acc);
        acc = fmaf(z[ 8], w2.x, acc);
        acc = fmaf(z[ 9], w2.y, acc);
        acc = fmaf(z[10], w2.z, acc);
        acc = fmaf(z[11], w2.w, acc);
        acc = fmaf(z[12], w3.x, acc);
        acc = fmaf(z[13], w3.y, acc);
        acc = fmaf(z[14], w3.z, acc);
        acc = fmaf(z[15], w3.w, acc);
        out[o] = acc;
    }

    float4* yp = y4 + (size_t)token * 4;
    yp[0] = make_float4(out[ 0], out[ 1], out[ 2], out[ 3]);
    yp[1] = make_float4(out[ 4], out[ 5], out[ 6], out[ 7]);
    yp[2] = make_float4(out[ 8], out[ 9], out[10], out[11]);
    yp[3] = make_float4(out[12], out[13], out[14], out[15]);
}

extern "C" void kernel_launch(void* const* d_in, const int* in_sizes, int n_in,
                              void* d_out, int out_size)
{
    const float4* x4    = (const float4*)d_in[0];
    const float*  theta = (const float*) d_in[1];
    const float4* w4    = (const float4*)d_in[2];
    float4*       y4    = (float4*)d_out;

    qattn_kernel<<<TOKENS / BLOCK, BLOCK>>>(x4, theta, w4, y4);
}